// round 3
// baseline (speedup 1.0000x reference)
#include <cuda_runtime.h>

static constexpr int FEAS = 4096;
static constexpr int K    = 64;
static constexpr int NCROSS_BLKS = 64;   // each reduces 64 rows of cross
static constexpr int ROWS_PER_BLK = 4;   // 2 warps (64 lanes) per row, 256 thr

// Persistent device state (zero-init at load; every replay restores it).
__device__ float g_colsum[K];
__device__ float g_diag;
__device__ float g_scalar;        // 0.5*(|colsum|^2 + |V|_F^2) + bias
__device__ int   g_cross_count;
__device__ int   g_done;
__device__ int   g_mv_count;

__global__ __launch_bounds__(256, 8)
void fm_fused_kernel(const float4* __restrict__ x,
                     const float4* __restrict__ w,
                     const float*  __restrict__ cross,
                     const float*  __restrict__ linear_b,
                     float* __restrict__ out,
                     int n_mv_blocks) {
    const int tid  = threadIdx.x;
    const int lane = tid & 31;
    const int warp = tid >> 5;

    if (blockIdx.x < NCROSS_BLKS) {
        // ---------------- cross slice: 64 rows x 64 cols --------------------
        __shared__ float s_col[256];
        __shared__ float s_diag[256];
        __shared__ int   s_last;

        const int k    = tid & (K - 1);
        const int ty   = tid >> 6;
        const int base = blockIdx.x * 64;

        float col = 0.f, diag = 0.f;
        #pragma unroll 4
        for (int f = base + ty; f < base + 64; f += 4) {
            float v = cross[f * K + k];
            col  += v;
            diag += v * v;
        }
        s_col[tid]  = col;
        s_diag[tid] = diag;
        __syncthreads();

        if (tid < K) {
            float cs = s_col[tid] + s_col[tid + 64] + s_col[tid + 128] + s_col[tid + 192];
            atomicAdd(&g_colsum[tid], cs);
        }
        if (warp == 0) {
            float d = 0.f;
            #pragma unroll
            for (int i = 0; i < 8; i++) d += s_diag[lane + i * 32];
            #pragma unroll
            for (int o = 16; o > 0; o >>= 1) d += __shfl_down_sync(0xffffffffu, d, o);
            if (lane == 0) atomicAdd(&g_diag, d);
        }
        __threadfence();
        __syncthreads();

        if (tid == 0)
            s_last = (atomicAdd(&g_cross_count, 1) == NCROSS_BLKS - 1) ? 1 : 0;
        __syncthreads();

        if (s_last) {
            if (warp == 0) {
                float a = g_colsum[lane];
                float b = g_colsum[lane + 32];
                float t = a * a + b * b;
                #pragma unroll
                for (int o = 16; o > 0; o >>= 1) t += __shfl_down_sync(0xffffffffu, t, o);
                if (lane == 0) {
                    g_scalar = 0.5f * (t + g_diag) + linear_b[0];
                    __threadfence();
                    atomicExch(&g_done, 1);
                }
            }
            __syncthreads();
            if (tid < K) g_colsum[tid] = 0.f;
            if (tid == 0) { g_diag = 0.f; g_cross_count = 0; }
        }
        return;
    }

    // ---------------- matvec: 64 lanes per row, 4 rows per block ------------
    __shared__ float4 s_w[FEAS / 4];     // 16KB: weights staged once per block
    __shared__ float  s_part[8];

    #pragma unroll
    for (int i = 0; i < 4; i++)
        s_w[tid + i * 256] = w[tid + i * 256];
    __syncthreads();

    const int sub = tid & 63;            // lane within the 64-lane row group
    const int rib = tid >> 6;            // row-in-block 0..3
    const int row = (blockIdx.x - NCROSS_BLKS) * ROWS_PER_BLK + rib;
    const float4* xr = x + (size_t)row * (FEAS / 4);

    float a0 = 0.f, a1 = 0.f;
    #pragma unroll
    for (int j = 0; j < 16; j += 2) {    // 16 float4 per thread
        const int i0 = sub + j * 64;
        const int i1 = sub + (j + 1) * 64;
        float4 xv0 = xr[i0];
        float4 xv1 = xr[i1];
        float4 wv0 = s_w[i0];
        float4 wv1 = s_w[i1];
        a0 += xv0.x * wv0.x + xv0.y * wv0.y + xv0.z * wv0.z + xv0.w * wv0.w;
        a1 += xv1.x * wv1.x + xv1.y * wv1.y + xv1.z * wv1.z + xv1.w * wv1.w;
    }
    float acc = a0 + a1;

    #pragma unroll
    for (int o = 16; o > 0; o >>= 1)
        acc += __shfl_down_sync(0xffffffffu, acc, o);

    if (lane == 0) s_part[warp] = acc;
    __syncthreads();

    if (sub == 0) {                       // one leader per row
        float total = s_part[rib * 2] + s_part[rib * 2 + 1];
        while (*(volatile int*)&g_done == 0) __nanosleep(64);
        __threadfence();                  // acquire
        float z = total + g_scalar;
        out[row] = 1.f / (1.f + __expf(-z));
    }
    __syncthreads();                      // all leaders done before reset vote
    if (tid == 0) {
        if (atomicAdd(&g_mv_count, 1) == n_mv_blocks - 1) {
            g_done = 0;
            g_mv_count = 0;
        }
    }
}

extern "C" void kernel_launch(void* const* d_in, const int* in_sizes, int n_in,
                              void* d_out, int out_size) {
    const float* x        = (const float*)d_in[0];  // (B, FEAS)
    const float* cross    = (const float*)d_in[1];  // (FEAS, 1, K)
    const float* linear_w = (const float*)d_in[2];  // (1, FEAS)
    const float* linear_b = (const float*)d_in[3];  // (1,)
    float* out = (float*)d_out;

    const int B = in_sizes[0] / FEAS;               // 4096
    const int n_mv = B / ROWS_PER_BLK;              // 1024

    fm_fused_kernel<<<NCROSS_BLKS + n_mv, 256>>>(
        (const float4*)x, (const float4*)linear_w, cross, linear_b, out, n_mv);
}

// round 4
// speedup vs baseline: 1.3233x; 1.3233x over previous
#include <cuda_runtime.h>

static constexpr int FEAS = 4096;
static constexpr int K    = 64;
static constexpr int NCROSS_BLKS = 64;   // each reduces 64 rows of cross
static constexpr int ROWS_PER_BLK = 8;   // warp-per-row, 256 threads

// Persistent device state (zero-init at load; every replay restores it).
__device__ float g_colsum[K];
__device__ float g_diag;
__device__ float g_scalar;        // 0.5*(|colsum|^2 + |V|_F^2) + bias
__device__ int   g_cross_count;
__device__ int   g_done;
__device__ int   g_mv_count;

__global__ __launch_bounds__(256, 8)
void fm_fused_kernel(const float4* __restrict__ x,
                     const float4* __restrict__ w,
                     const float*  __restrict__ cross,
                     const float*  __restrict__ linear_b,
                     float* __restrict__ out,
                     int n_mv_blocks) {
    const int tid  = threadIdx.x;
    const int lane = tid & 31;
    const int warp = tid >> 5;

    if (blockIdx.x < NCROSS_BLKS) {
        // ---------------- cross slice: 64 rows x 64 cols --------------------
        __shared__ float s_col[256];
        __shared__ float s_diag[256];
        __shared__ int   s_last;

        const int k    = tid & (K - 1);
        const int ty   = tid >> 6;
        const int base = blockIdx.x * 64;

        float col = 0.f, diag = 0.f;
        #pragma unroll 4
        for (int f = base + ty; f < base + 64; f += 4) {
            float v = cross[f * K + k];
            col  += v;
            diag += v * v;
        }
        s_col[tid]  = col;
        s_diag[tid] = diag;
        __syncthreads();

        if (tid < K) {
            float cs = s_col[tid] + s_col[tid + 64] + s_col[tid + 128] + s_col[tid + 192];
            atomicAdd(&g_colsum[tid], cs);
        }
        if (warp == 0) {
            float d = 0.f;
            #pragma unroll
            for (int i = 0; i < 8; i++) d += s_diag[lane + i * 32];
            #pragma unroll
            for (int o = 16; o > 0; o >>= 1) d += __shfl_down_sync(0xffffffffu, d, o);
            if (lane == 0) atomicAdd(&g_diag, d);
        }
        __threadfence();
        __syncthreads();

        if (tid == 0)
            s_last = (atomicAdd(&g_cross_count, 1) == NCROSS_BLKS - 1) ? 1 : 0;
        __syncthreads();

        if (s_last) {
            if (warp == 0) {
                float a = g_colsum[lane];
                float b = g_colsum[lane + 32];
                float t = a * a + b * b;
                #pragma unroll
                for (int o = 16; o > 0; o >>= 1) t += __shfl_down_sync(0xffffffffu, t, o);
                if (lane == 0) {
                    g_scalar = 0.5f * (t + g_diag) + linear_b[0];
                    __threadfence();
                    atomicExch(&g_done, 1);
                }
            }
            __syncthreads();
            if (tid < K) g_colsum[tid] = 0.f;
            if (tid == 0) { g_diag = 0.f; g_cross_count = 0; }
        }
        return;
    }

    // ---------------- matvec: warp-per-row, 8 rows/block --------------------
    // 32 float4 per lane, processed as 2 batches of (4 x-loads + 4 w-loads)
    // into 4 independent accumulators => 8 LDG.128 front-batched per batch.
    const int row = (blockIdx.x - NCROSS_BLKS) * ROWS_PER_BLK + warp;
    const float4* xr = x + (size_t)row * (FEAS / 4);

    float acc0 = 0.f, acc1 = 0.f, acc2 = 0.f, acc3 = 0.f;
    #pragma unroll
    for (int j = 0; j < 8; j += 4) {               // 2 outer batches
        float4 xv[4], wv[4];
        #pragma unroll
        for (int u = 0; u < 4; u++) {
            const int idx = lane + (j + u) * 128;  // hmm see below
            (void)idx;
        }
        // indices: lane + (j+u)*32*4?  Row has 1024 float4; lane-strided by 32.
        #pragma unroll
        for (int u = 0; u < 4; u++) xv[u] = xr[lane + (j + u) * 32];
        #pragma unroll
        for (int u = 0; u < 4; u++) wv[u] = __ldg(&w[lane + (j + u) * 32]);
        acc0 += xv[0].x*wv[0].x + xv[0].y*wv[0].y + xv[0].z*wv[0].z + xv[0].w*wv[0].w;
        acc1 += xv[1].x*wv[1].x + xv[1].y*wv[1].y + xv[1].z*wv[1].z + xv[1].w*wv[1].w;
        acc2 += xv[2].x*wv[2].x + xv[2].y*wv[2].y + xv[2].z*wv[2].z + xv[2].w*wv[2].w;
        acc3 += xv[3].x*wv[3].x + xv[3].y*wv[3].y + xv[3].z*wv[3].z + xv[3].w*wv[3].w;
    }
    #pragma unroll
    for (int j = 8; j < 32; j += 4) {              // remaining 6 batches
        float4 xv[4], wv[4];
        #pragma unroll
        for (int u = 0; u < 4; u++) xv[u] = xr[lane + (j + u) * 32];
        #pragma unroll
        for (int u = 0; u < 4; u++) wv[u] = __ldg(&w[lane + (j + u) * 32]);
        acc0 += xv[0].x*wv[0].x + xv[0].y*wv[0].y + xv[0].z*wv[0].z + xv[0].w*wv[0].w;
        acc1 += xv[1].x*wv[1].x + xv[1].y*wv[1].y + xv[1].z*wv[1].z + xv[1].w*wv[1].w;
        acc2 += xv[2].x*wv[2].x + xv[2].y*wv[2].y + xv[2].z*wv[2].z + xv[2].w*wv[2].w;
        acc3 += xv[3].x*wv[3].x + xv[3].y*wv[3].y + xv[3].z*wv[3].z + xv[3].w*wv[3].w;
    }
    float acc = (acc0 + acc1) + (acc2 + acc3);

    #pragma unroll
    for (int o = 16; o > 0; o >>= 1)
        acc += __shfl_down_sync(0xffffffffu, acc, o);

    if (lane == 0) {
        while (*(volatile int*)&g_done == 0) __nanosleep(64);
        __threadfence();                           // acquire
        float z = acc + g_scalar;
        out[row] = 1.f / (1.f + __expf(-z));
    }
    __syncthreads();
    if (tid == 0) {
        if (atomicAdd(&g_mv_count, 1) == n_mv_blocks - 1) {
            g_done = 0;
            g_mv_count = 0;
        }
    }
}

extern "C" void kernel_launch(void* const* d_in, const int* in_sizes, int n_in,
                              void* d_out, int out_size) {
    const float* x        = (const float*)d_in[0];  // (B, FEAS)
    const float* cross    = (const float*)d_in[1];  // (FEAS, 1, K)
    const float* linear_w = (const float*)d_in[2];  // (1, FEAS)
    const float* linear_b = (const float*)d_in[3];  // (1,)
    float* out = (float*)d_out;

    const int B = in_sizes[0] / FEAS;               // 4096
    const int n_mv = B / ROWS_PER_BLK;              // 512

    fm_fused_kernel<<<NCROSS_BLKS + n_mv, 256>>>(
        (const float4*)x, (const float4*)linear_w, cross, linear_b, out, n_mv);
}